// round 1
// baseline (speedup 1.0000x reference)
#include <cuda_runtime.h>
#include <cstdint>

#define B_   16
#define C_   64
#define H_   80
#define W_   80
#define N_   32
#define HW_  (H_ * W_)
#define TOT_ (B_ * C_ * H_ * W_)

struct MatchRec { int valid; int lab; int mi; int mj; };

__device__ MatchRec g_match[B_ * N_];
__device__ double g_sum_conf;
__device__ double g_sum_l1;
__device__ double g_sum_giou;
__device__ int    g_num_pos;

__global__ void zero_kernel() {
    g_sum_conf = 0.0;
    g_sum_l1   = 0.0;
    g_sum_giou = 0.0;
    g_num_pos  = 0;
}

__device__ __forceinline__ float giou_f(float4 p, float4 q) {
    float a1 = (p.z - p.x) * (p.w - p.y);
    float a2 = (q.z - q.x) * (q.w - q.y);
    float ltx = fmaxf(p.x, q.x), lty = fmaxf(p.y, q.y);
    float rbx = fminf(p.z, q.z), rby = fminf(p.w, q.w);
    float wx = fmaxf(rbx - ltx, 0.0f), wy = fmaxf(rby - lty, 0.0f);
    float inter = wx * wy;
    float uni = a1 + a2 - inter;
    float iou = inter / uni;
    float ex = fminf(p.x, q.x), ey = fminf(p.y, q.y);
    float fx = fmaxf(p.z, q.z), fy = fmaxf(p.w, q.w);
    float ew = fmaxf(fx - ex, 0.0f), eh = fmaxf(fy - ey, 0.0f);
    float ae = ew * eh;
    return iou - (ae - uni) / ae;
}

// One block per (b, g): argmax of GIoU over the matched channel's H*W grid.
__global__ void assign_kernel(const float* __restrict__ pred,
                              const float* __restrict__ gtb,
                              const int*   __restrict__ gtl) {
    int bg = blockIdx.x;
    int b = bg / N_;
    int g = bg % N_;
    int lab = gtl[b * N_ + g];
    float4 gq = reinterpret_cast<const float4*>(gtb)[b * N_ + g];
    const float4* pc = reinterpret_cast<const float4*>(
        pred + ((size_t)(b * C_ + lab)) * HW_ * 4);

    float best = -1e30f;
    int bidx = 0;
    for (int idx = threadIdx.x; idx < HW_; idx += blockDim.x) {
        float v = giou_f(pc[idx], gq);
        if (v > best) { best = v; bidx = idx; }   // keeps smallest idx per thread
    }

    __shared__ float sv[256];
    __shared__ int   si[256];
    sv[threadIdx.x] = best;
    si[threadIdx.x] = bidx;
    __syncthreads();
    for (int s = 128; s > 0; s >>= 1) {
        if (threadIdx.x < s) {
            float v2 = sv[threadIdx.x + s];
            int   i2 = si[threadIdx.x + s];
            if (v2 > sv[threadIdx.x] ||
                (v2 == sv[threadIdx.x] && i2 < si[threadIdx.x])) {
                sv[threadIdx.x] = v2;
                si[threadIdx.x] = i2;
            }
        }
        __syncthreads();
    }
    if (threadIdx.x == 0) {
        MatchRec r;
        r.valid = (sv[0] > 0.3f) ? 1 : 0;
        r.lab = lab;
        r.mi = si[0] / W_;
        r.mj = si[0] % W_;
        g_match[bg] = r;
    }
}

__device__ __forceinline__ float block_reduce_sum(float v) {
    __shared__ float sh[32];
    int lane = threadIdx.x & 31;
    int wid  = threadIdx.x >> 5;
    #pragma unroll
    for (int o = 16; o > 0; o >>= 1) v += __shfl_down_sync(0xffffffffu, v, o);
    if (lane == 0) sh[wid] = v;
    __syncthreads();
    int nwarps = blockDim.x >> 5;
    v = (threadIdx.x < nwarps) ? sh[lane] : 0.0f;
    if (wid == 0) {
        #pragma unroll
        for (int o = 16; o > 0; o >>= 1) v += __shfl_down_sync(0xffffffffu, v, o);
    }
    return v;
}

__device__ __forceinline__ float focal_neg(float c) {
    // t = 0 term: 0.75 * p^2 * (-log(1-p))
    float p = fminf(fmaxf(c, 1e-6f), 1.0f - 1e-6f);
    return 0.75f * p * p * (-__logf(1.0f - p));
}

// Focal loss over the whole confidence tensor assuming t = 0 everywhere.
__global__ void focal_kernel(const float* __restrict__ conf) {
    const float4* c4 = reinterpret_cast<const float4*>(conf);
    const int n4 = TOT_ / 4;
    float acc = 0.0f;
    int stride = gridDim.x * blockDim.x;
    for (int i = blockIdx.x * blockDim.x + threadIdx.x; i < n4; i += stride) {
        float4 v = c4[i];
        acc += focal_neg(v.x);
        acc += focal_neg(v.y);
        acc += focal_neg(v.z);
        acc += focal_neg(v.w);
    }
    float bsum = block_reduce_sum(acc);
    if (threadIdx.x == 0) atomicAdd(&g_sum_conf, (double)bsum);
}

// Sparse positives: one block per batch. Enumerates window cells, resolves
// ownership to the max-g covering gt (scan overwrite semantics), computes
// l1 + giou + focal correction (t=1 minus the t=0 already counted).
__global__ void pos_kernel(const float* __restrict__ pred,
                           const float* __restrict__ conf,
                           const float* __restrict__ gtb) {
    int b = blockIdx.x;
    __shared__ MatchRec recs[N_];
    __shared__ float4   gbox[N_];
    if (threadIdx.x < N_) {
        recs[threadIdx.x] = g_match[b * N_ + threadIdx.x];
        gbox[threadIdx.x] = reinterpret_cast<const float4*>(gtb)[b * N_ + threadIdx.x];
    }
    __syncthreads();

    float sl1 = 0.0f, sgi = 0.0f, scf = 0.0f;
    int cnt = 0;

    for (int cell = threadIdx.x; cell < N_ * 16; cell += blockDim.x) {
        int g = cell >> 4;
        int w = cell & 15;
        MatchRec r = recs[g];
        if (!r.valid) continue;
        int i = r.mi - 2 + (w >> 2);
        int j = r.mj - 2 + (w & 3);
        if (i < 0 || i >= H_ || j < 0 || j >= W_) continue;

        bool owned = true;
        for (int g2 = g + 1; g2 < N_; g2++) {
            MatchRec r2 = recs[g2];
            if (r2.valid && r2.lab == r.lab &&
                i >= r2.mi - 2 && i <= r2.mi + 1 &&
                j >= r2.mj - 2 && j <= r2.mj + 1) {
                owned = false;
                break;
            }
        }
        if (!owned) continue;

        size_t off = (((size_t)b * C_ + r.lab) * HW_ + (size_t)i * W_ + j);
        float4 pb = reinterpret_cast<const float4*>(pred)[off];
        float4 gq = gbox[g];

        float l1 = 0.25f * (fabsf(pb.x - gq.x) + fabsf(pb.y - gq.y) +
                            fabsf(pb.z - gq.z) + fabsf(pb.w - gq.w));
        float gi = giou_f(pb, gq);

        float c = conf[off];
        float p = fminf(fmaxf(c, 1e-6f), 1.0f - 1e-6f);
        float f1 = 0.25f * (1.0f - p) * (1.0f - p) * (-__logf(p));
        float f0 = 0.75f * p * p * (-__logf(1.0f - p));

        sl1 += l1;
        sgi += (1.0f - gi);
        scf += (f1 - f0);
        cnt += 1;
    }

    float bl1 = block_reduce_sum(sl1);
    __syncthreads();
    float bgi = block_reduce_sum(sgi);
    __syncthreads();
    float bcf = block_reduce_sum(scf);
    __syncthreads();
    __shared__ int scnt;
    if (threadIdx.x == 0) scnt = 0;
    __syncthreads();
    if (cnt) atomicAdd(&scnt, cnt);
    __syncthreads();
    if (threadIdx.x == 0) {
        atomicAdd(&g_sum_l1,   (double)bl1);
        atomicAdd(&g_sum_giou, (double)bgi);
        atomicAdd(&g_sum_conf, (double)bcf);
        atomicAdd(&g_num_pos,  scnt);
    }
}

__global__ void finalize_kernel(float* __restrict__ out) {
    int np = g_num_pos;
    float denom = (float)(np > 1 ? np : 1);
    float l1 = (float)g_sum_l1 / denom;
    float gi = (float)g_sum_giou / denom;
    float cf = (float)(g_sum_conf / (double)TOT_);
    out[0] = l1;
    out[1] = gi;
    out[2] = cf;
    out[3] = l1 + 2.0f * gi + cf;
    out[4] = (float)np / (float)TOT_;
}

extern "C" void kernel_launch(void* const* d_in, const int* in_sizes, int n_in,
                              void* d_out, int out_size) {
    const float* pred = (const float*)d_in[0];   // [B,C,H,W,4]
    const float* conf = (const float*)d_in[1];   // [B,C,H,W]
    // d_in[2] = cam (unused by the loss)
    const float* gtb  = (const float*)d_in[3];   // [B,N,4]
    const int*   gtl  = (const int*)d_in[4];     // [B,N]
    float* out = (float*)d_out;

    zero_kernel<<<1, 1>>>();
    assign_kernel<<<B_ * N_, 256>>>(pred, gtb, gtl);
    focal_kernel<<<2048, 256>>>(conf);
    pos_kernel<<<B_, 128>>>(pred, conf, gtb);
    finalize_kernel<<<1, 1>>>(out);
}

// round 2
// speedup vs baseline: 1.2339x; 1.2339x over previous
#include <cuda_runtime.h>
#include <cstdint>

#define B_   16
#define C_   64
#define H_   80
#define W_   80
#define N_   32
#define HW_  (H_ * W_)
#define TOT_ (B_ * C_ * H_ * W_)

#define ASSIGN_BLOCKS (B_ * N_)          // 512
#define FOCAL_BLOCKS  1024
#define K1_BLOCKS     (ASSIGN_BLOCKS + FOCAL_BLOCKS)
#define FOCAL_CHUNK   ((TOT_ / 4) / FOCAL_BLOCKS)   // 1600 float4 per block
#define POS_BLOCKS    64                  // 4 blocks per batch, 128 cells each

// Per-slot partials: every slot is written every run -> no zeroing kernel needed.
__device__ unsigned g_match_p[ASSIGN_BLOCKS];
__device__ double   g_focal_part[FOCAL_BLOCKS];
__device__ double   g_pos_l1[POS_BLOCKS];
__device__ double   g_pos_gi[POS_BLOCKS];
__device__ double   g_pos_cf[POS_BLOCKS];
__device__ int      g_pos_cnt[POS_BLOCKS];
__device__ int      g_done = 0;           // self-resetting arrival counter

__device__ __forceinline__ float giou_f(float4 p, float4 q, float a2) {
    float a1 = (p.z - p.x) * (p.w - p.y);
    float ltx = fmaxf(p.x, q.x), lty = fmaxf(p.y, q.y);
    float rbx = fminf(p.z, q.z), rby = fminf(p.w, q.w);
    float wx = fmaxf(rbx - ltx, 0.0f), wy = fmaxf(rby - lty, 0.0f);
    float inter = wx * wy;
    float uni = a1 + a2 - inter;
    float iou = inter / uni;
    float ex = fminf(p.x, q.x), ey = fminf(p.y, q.y);
    float fx = fmaxf(p.z, q.z), fy = fmaxf(p.w, q.w);
    float ew = fmaxf(fx - ex, 0.0f), eh = fmaxf(fy - ey, 0.0f);
    float ae = ew * eh;
    return iou - (ae - uni) / ae;
}

__device__ __forceinline__ float focal_neg(float c) {
    // t = 0 term: 0.75 * p^2 * (-log(1-p))
    float p = fminf(fmaxf(c, 1e-6f), 1.0f - 1e-6f);
    return 0.75f * p * p * (-__logf(1.0f - p));
}

// Block-wide float sum, works for blockDim 128 or 256.
__device__ __forceinline__ float block_reduce_sum(float v, float* sh32) {
    int lane = threadIdx.x & 31;
    int wid  = threadIdx.x >> 5;
    #pragma unroll
    for (int o = 16; o > 0; o >>= 1) v += __shfl_down_sync(0xffffffffu, v, o);
    if (lane == 0) sh32[wid] = v;
    __syncthreads();
    int nwarps = blockDim.x >> 5;
    v = (threadIdx.x < nwarps) ? sh32[lane] : 0.0f;
    if (wid == 0) {
        #pragma unroll
        for (int o = 16; o > 0; o >>= 1) v += __shfl_down_sync(0xffffffffu, v, o);
    }
    return v;
}

// ---------------------------------------------------------------------------
// K1: blocks [0,512) do per-(b,g) GIoU argmax assignment;
//     blocks [512,1536) do the dense t=0 focal sum over `conf`.
// ---------------------------------------------------------------------------
__global__ void k1_kernel(const float* __restrict__ pred,
                          const float* __restrict__ conf,
                          const float* __restrict__ gtb,
                          const int*   __restrict__ gtl) {
    __shared__ float sv[256];
    __shared__ int   si[256];
    int tid = threadIdx.x;

    if (blockIdx.x < ASSIGN_BLOCKS) {
        int bg = blockIdx.x;
        int b = bg >> 5;                 // N_ = 32
        int lab = gtl[bg];
        float4 gq = reinterpret_cast<const float4*>(gtb)[bg];
        float a2 = (gq.z - gq.x) * (gq.w - gq.y);
        const float4* pc = reinterpret_cast<const float4*>(pred)
                           + (size_t)(b * C_ + lab) * HW_;

        float best = -1e30f;
        int bidx = 0;
        for (int idx = tid; idx < HW_; idx += 256) {
            float v = giou_f(pc[idx], gq, a2);
            if (v > best) { best = v; bidx = idx; }  // smallest idx per thread
        }
        sv[tid] = best;
        si[tid] = bidx;
        __syncthreads();
        for (int s = 128; s > 0; s >>= 1) {
            if (tid < s) {
                float v2 = sv[tid + s];
                int   i2 = si[tid + s];
                if (v2 > sv[tid] || (v2 == sv[tid] && i2 < si[tid])) {
                    sv[tid] = v2;
                    si[tid] = i2;
                }
            }
            __syncthreads();
        }
        if (tid == 0) {
            int idx = si[0];
            int mi = idx / W_, mj = idx % W_;
            unsigned valid = (sv[0] > 0.3f) ? 1u : 0u;
            g_match_p[bg] = (valid << 30) | ((unsigned)lab << 16)
                          | ((unsigned)mi << 8) | (unsigned)mj;
        }
    } else {
        int fb = blockIdx.x - ASSIGN_BLOCKS;
        const float4* c4 = reinterpret_cast<const float4*>(conf);
        int start = fb * FOCAL_CHUNK;
        float acc = 0.0f;
        for (int i = start + tid; i < start + FOCAL_CHUNK; i += 256) {
            float4 v = c4[i];
            acc += focal_neg(v.x);
            acc += focal_neg(v.y);
            acc += focal_neg(v.z);
            acc += focal_neg(v.w);
        }
        float bsum = block_reduce_sum(acc, sv);
        if (tid == 0) g_focal_part[fb] = (double)bsum;
    }
}

// ---------------------------------------------------------------------------
// K2: one thread per window cell (B*N*16 = 8192 cells, 64 blocks x 128).
//     Branch-free ownership resolution, then sparse l1/giou/focal-correction.
//     Last block to arrive performs the final reduction + output write.
// ---------------------------------------------------------------------------
__global__ void k2_kernel(const float* __restrict__ pred,
                          const float* __restrict__ conf,
                          const float* __restrict__ gtb,
                          float* __restrict__ out) {
    __shared__ unsigned recs[N_];
    __shared__ float4   gbox[N_];
    __shared__ float    sh32[32];
    int tid = threadIdx.x;
    int b = blockIdx.x >> 2;
    int cell = ((blockIdx.x & 3) << 7) + tid;   // 0..511 within batch

    if (tid < N_) {
        recs[tid] = g_match_p[b * N_ + tid];
        gbox[tid] = reinterpret_cast<const float4*>(gtb)[b * N_ + tid];
    }
    __syncthreads();

    int g = cell >> 4;
    int w = cell & 15;
    unsigned r = recs[g];
    int lab = (r >> 16) & 63;
    int mi  = (r >> 8) & 255;
    int mj  = r & 255;
    int i = mi - 2 + (w >> 2);
    int j = mj - 2 + (w & 3);
    bool act = ((r >> 30) & 1u) && ((unsigned)i < H_) && ((unsigned)j < W_);

    // Ownership: no later valid gt with the same label covers this cell.
    #pragma unroll
    for (int g2 = 0; g2 < N_; g2++) {
        unsigned r2 = recs[g2];
        int mi2 = (r2 >> 8) & 255;
        int mj2 = r2 & 255;
        bool cover = (g2 > g)
                   & (int)((r2 >> 30) & 1u)
                   & (((r2 ^ r) & 0x3F0000u) == 0u)
                   & ((unsigned)(i - mi2 + 2) < 4u)
                   & ((unsigned)(j - mj2 + 2) < 4u);
        act &= !cover;
    }

    float sl1 = 0.0f, sgi = 0.0f, scf = 0.0f;
    int cnt = 0;
    if (act) {
        size_t off = (((size_t)b * C_ + lab) * HW_ + (size_t)i * W_ + j);
        float4 pb = reinterpret_cast<const float4*>(pred)[off];
        float4 gq = gbox[g];
        float a2 = (gq.z - gq.x) * (gq.w - gq.y);

        sl1 = 0.25f * (fabsf(pb.x - gq.x) + fabsf(pb.y - gq.y) +
                       fabsf(pb.z - gq.z) + fabsf(pb.w - gq.w));
        sgi = 1.0f - giou_f(pb, gq, a2);

        float c = conf[off];
        float p = fminf(fmaxf(c, 1e-6f), 1.0f - 1e-6f);
        float f1 = 0.25f * (1.0f - p) * (1.0f - p) * (-__logf(p));
        float f0 = 0.75f * p * p * (-__logf(1.0f - p));
        scf = f1 - f0;
        cnt = 1;
    }

    float bl1 = block_reduce_sum(sl1, sh32);
    __syncthreads();
    float bgi = block_reduce_sum(sgi, sh32);
    __syncthreads();
    float bcf = block_reduce_sum(scf, sh32);
    __syncthreads();
    float bcnt = block_reduce_sum((float)cnt, sh32);

    if (tid == 0) {
        g_pos_l1[blockIdx.x]  = (double)bl1;
        g_pos_gi[blockIdx.x]  = (double)bgi;
        g_pos_cf[blockIdx.x]  = (double)bcf;
        g_pos_cnt[blockIdx.x] = (int)(bcnt + 0.5f);
    }

    // ---- last-block finalize ----
    __shared__ int is_last;
    __threadfence();
    __syncthreads();
    if (tid == 0) {
        int t = atomicAdd(&g_done, 1);
        is_last = (t == (int)gridDim.x - 1) ? 1 : 0;
    }
    __syncthreads();
    if (!is_last) return;

    double l1 = 0.0, gi = 0.0, cf = 0.0;
    int np = 0;
    for (int k = tid; k < POS_BLOCKS; k += 128) {
        l1 += g_pos_l1[k];
        gi += g_pos_gi[k];
        cf += g_pos_cf[k];
        np += g_pos_cnt[k];
    }
    for (int k = tid; k < FOCAL_BLOCKS; k += 128) cf += g_focal_part[k];

    __shared__ double sd[128];
    __shared__ int    sn[128];
    // l1
    sd[tid] = l1; __syncthreads();
    for (int s = 64; s > 0; s >>= 1) { if (tid < s) sd[tid] += sd[tid + s]; __syncthreads(); }
    l1 = sd[0]; __syncthreads();
    // gi
    sd[tid] = gi; __syncthreads();
    for (int s = 64; s > 0; s >>= 1) { if (tid < s) sd[tid] += sd[tid + s]; __syncthreads(); }
    gi = sd[0]; __syncthreads();
    // cf
    sd[tid] = cf; __syncthreads();
    for (int s = 64; s > 0; s >>= 1) { if (tid < s) sd[tid] += sd[tid + s]; __syncthreads(); }
    cf = sd[0]; __syncthreads();
    // np
    sn[tid] = np; __syncthreads();
    for (int s = 64; s > 0; s >>= 1) { if (tid < s) sn[tid] += sn[tid + s]; __syncthreads(); }
    np = sn[0];

    if (tid == 0) {
        float denom = (float)(np > 1 ? np : 1);
        float fl1 = (float)l1 / denom;
        float fgi = (float)gi / denom;
        float fcf = (float)(cf / (double)TOT_);
        out[0] = fl1;
        out[1] = fgi;
        out[2] = fcf;
        out[3] = fl1 + 2.0f * fgi + fcf;
        out[4] = (float)np / (float)TOT_;
        g_done = 0;   // restore invariant for next replay
    }
}

extern "C" void kernel_launch(void* const* d_in, const int* in_sizes, int n_in,
                              void* d_out, int out_size) {
    const float* pred = (const float*)d_in[0];   // [B,C,H,W,4]
    const float* conf = (const float*)d_in[1];   // [B,C,H,W]
    // d_in[2] = cam (unused by the loss)
    const float* gtb  = (const float*)d_in[3];   // [B,N,4]
    const int*   gtl  = (const int*)d_in[4];     // [B,N]
    float* out = (float*)d_out;

    k1_kernel<<<K1_BLOCKS, 256>>>(pred, conf, gtb, gtl);
    k2_kernel<<<POS_BLOCKS, 128>>>(pred, conf, gtb, out);
}

// round 3
// speedup vs baseline: 1.3135x; 1.0645x over previous
#include <cuda_runtime.h>
#include <cstdint>

#define B_   16
#define C_   64
#define H_   80
#define W_   80
#define N_   32
#define HW_  (H_ * W_)
#define TOT_ (B_ * C_ * H_ * W_)

#define ASSIGN_BLOCKS (B_ * N_)           // 512
#define FOCAL_BLOCKS  1024
#define GRID_BLOCKS   (ASSIGN_BLOCKS + FOCAL_BLOCKS)   // 1536
#define N4_           (TOT_ / 4)          // 409600 float4
#define FOCAL_CHUNK   (N4_ / FOCAL_BLOCKS) // 400 float4 per block

// Per-slot partials: every slot is written every run -> no zeroing needed.
__device__ unsigned g_match_p[ASSIGN_BLOCKS];
__device__ double   g_focal_part[FOCAL_BLOCKS];
__device__ double   g_pos_l1[B_];
__device__ double   g_pos_gi[B_];
__device__ double   g_pos_cf[B_];
__device__ int      g_pos_cnt[B_];
__device__ int      g_batch_done[B_];     // self-resetting
__device__ int      g_done = 0;           // self-resetting

__device__ __forceinline__ float giou_f(float4 p, float4 q, float a2) {
    float a1 = (p.z - p.x) * (p.w - p.y);
    float ltx = fmaxf(p.x, q.x), lty = fmaxf(p.y, q.y);
    float rbx = fminf(p.z, q.z), rby = fminf(p.w, q.w);
    float wx = fmaxf(rbx - ltx, 0.0f), wy = fmaxf(rby - lty, 0.0f);
    float inter = wx * wy;
    float uni = a1 + a2 - inter;
    float iou = inter / uni;
    float ex = fminf(p.x, q.x), ey = fminf(p.y, q.y);
    float fx = fmaxf(p.z, q.z), fy = fmaxf(p.w, q.w);
    float ew = fmaxf(fx - ex, 0.0f), eh = fmaxf(fy - ey, 0.0f);
    float ae = ew * eh;
    return iou - (ae - uni) / ae;
}

__device__ __forceinline__ float focal_neg(float c) {
    // t = 0 term: 0.75 * p^2 * (-log(1-p))
    float p = fminf(fmaxf(c, 1e-6f), 1.0f - 1e-6f);
    return 0.75f * p * p * (-__logf(1.0f - p));
}

__device__ __forceinline__ float block_reduce_sum(float v, float* sh32) {
    int lane = threadIdx.x & 31;
    int wid  = threadIdx.x >> 5;
    #pragma unroll
    for (int o = 16; o > 0; o >>= 1) v += __shfl_down_sync(0xffffffffu, v, o);
    if (lane == 0) sh32[wid] = v;
    __syncthreads();
    v = (threadIdx.x < (blockDim.x >> 5)) ? sh32[lane] : 0.0f;
    if (wid == 0) {
        #pragma unroll
        for (int o = 16; o > 0; o >>= 1) v += __shfl_down_sync(0xffffffffu, v, o);
    }
    return v;
}

__global__ void fused_kernel(const float* __restrict__ pred,
                             const float* __restrict__ conf,
                             const float* __restrict__ gtb,
                             const int*   __restrict__ gtl,
                             float* __restrict__ out) {
    __shared__ float sv[256];
    __shared__ int   si[256];
    __shared__ float sh32[32];
    int tid = threadIdx.x;
    int bid = blockIdx.x;

    if (bid < ASSIGN_BLOCKS) {
        // ---------------- assignment for (b, g) ----------------
        int bg = bid;
        int b = bg >> 5;                  // N_ = 32
        int lab = gtl[bg];
        float4 gq = reinterpret_cast<const float4*>(gtb)[bg];
        float a2 = (gq.z - gq.x) * (gq.w - gq.y);
        const float4* pc = reinterpret_cast<const float4*>(pred)
                           + (size_t)(b * C_ + lab) * HW_;

        float best = -1e30f;
        int bidx = 0;
        for (int idx = tid; idx < HW_; idx += 256) {
            float v = giou_f(pc[idx], gq, a2);
            if (v > best) { best = v; bidx = idx; }  // keeps smallest idx
        }
        sv[tid] = best;
        si[tid] = bidx;
        __syncthreads();
        for (int s = 128; s > 0; s >>= 1) {
            if (tid < s) {
                float v2 = sv[tid + s];
                int   i2 = si[tid + s];
                if (v2 > sv[tid] || (v2 == sv[tid] && i2 < si[tid])) {
                    sv[tid] = v2;
                    si[tid] = i2;
                }
            }
            __syncthreads();
        }
        if (tid == 0) {
            int idx = si[0];
            int mi = idx / W_, mj = idx % W_;
            unsigned valid = (sv[0] > 0.3f) ? 1u : 0u;
            g_match_p[bg] = (valid << 30) | ((unsigned)lab << 16)
                          | ((unsigned)mi << 8) | (unsigned)mj;
        }

        // -------- per-batch arrival; finisher runs the pos phase --------
        __shared__ int batch_last;
        __threadfence();
        __syncthreads();
        if (tid == 0) {
            int t = atomicAdd(&g_batch_done[b], 1);
            batch_last = (t == N_ - 1) ? 1 : 0;
        }
        __syncthreads();

        if (batch_last) {
            __threadfence();   // acquire: see all 32 match records
            __shared__ unsigned recs[N_];
            __shared__ float4   gbox[N_];
            if (tid < N_) {
                recs[tid] = g_match_p[b * N_ + tid];
                gbox[tid] = reinterpret_cast<const float4*>(gtb)[b * N_ + tid];
            }
            __syncthreads();

            float sl1 = 0.0f, sgi = 0.0f, scf = 0.0f;
            int cnt = 0;
            #pragma unroll
            for (int half = 0; half < 2; half++) {
                int cell = (half << 8) + tid;       // 0..511
                int g = cell >> 4;
                int w = cell & 15;
                unsigned r = recs[g];
                int lab2 = (r >> 16) & 63;
                int mi  = (r >> 8) & 255;
                int mj  = r & 255;
                int i = mi - 2 + (w >> 2);
                int j = mj - 2 + (w & 3);
                bool act = ((r >> 30) & 1u) && ((unsigned)i < H_) && ((unsigned)j < W_);

                #pragma unroll
                for (int g2 = 0; g2 < N_; g2++) {
                    unsigned r2 = recs[g2];
                    int mi2 = (r2 >> 8) & 255;
                    int mj2 = r2 & 255;
                    bool cover = (g2 > g)
                               & (int)((r2 >> 30) & 1u)
                               & (((r2 ^ r) & 0x3F0000u) == 0u)
                               & ((unsigned)(i - mi2 + 2) < 4u)
                               & ((unsigned)(j - mj2 + 2) < 4u);
                    act &= !cover;
                }

                if (act) {
                    size_t off = (((size_t)b * C_ + lab2) * HW_ + (size_t)i * W_ + j);
                    float4 pb = reinterpret_cast<const float4*>(pred)[off];
                    float4 gq2 = gbox[g];
                    float a22 = (gq2.z - gq2.x) * (gq2.w - gq2.y);

                    sl1 += 0.25f * (fabsf(pb.x - gq2.x) + fabsf(pb.y - gq2.y) +
                                    fabsf(pb.z - gq2.z) + fabsf(pb.w - gq2.w));
                    sgi += 1.0f - giou_f(pb, gq2, a22);

                    float c = conf[off];
                    float p = fminf(fmaxf(c, 1e-6f), 1.0f - 1e-6f);
                    float f1 = 0.25f * (1.0f - p) * (1.0f - p) * (-__logf(p));
                    float f0 = 0.75f * p * p * (-__logf(1.0f - p));
                    scf += f1 - f0;
                    cnt += 1;
                }
            }

            float bl1 = block_reduce_sum(sl1, sh32);
            __syncthreads();
            float bgi = block_reduce_sum(sgi, sh32);
            __syncthreads();
            float bcf = block_reduce_sum(scf, sh32);
            __syncthreads();
            float bcnt = block_reduce_sum((float)cnt, sh32);
            if (tid == 0) {
                g_pos_l1[b]  = (double)bl1;
                g_pos_gi[b]  = (double)bgi;
                g_pos_cf[b]  = (double)bcf;
                g_pos_cnt[b] = (int)(bcnt + 0.5f);
                g_batch_done[b] = 0;    // reset for next replay
            }
        }
    } else {
        // ---------------- dense focal (t = 0) partial ----------------
        int fb = bid - ASSIGN_BLOCKS;
        const float4* c4 = reinterpret_cast<const float4*>(conf);
        int start = fb * FOCAL_CHUNK;
        float acc = 0.0f;
        for (int i = start + tid; i < start + FOCAL_CHUNK; i += 256) {
            float4 v = c4[i];
            acc += focal_neg(v.x);
            acc += focal_neg(v.y);
            acc += focal_neg(v.z);
            acc += focal_neg(v.w);
        }
        float bsum = block_reduce_sum(acc, sh32);
        if (tid == 0) g_focal_part[fb] = (double)bsum;
    }

    // ---------------- global last-block finalize ----------------
    __shared__ int is_last;
    __threadfence();
    __syncthreads();
    if (tid == 0) {
        int t = atomicAdd(&g_done, 1);
        is_last = (t == GRID_BLOCKS - 1) ? 1 : 0;
    }
    __syncthreads();
    if (!is_last) return;
    __threadfence();   // acquire

    double l1 = 0.0, gi = 0.0, cf = 0.0;
    int np = 0;
    for (int k = tid; k < FOCAL_BLOCKS; k += 256) cf += g_focal_part[k];
    if (tid < B_) {
        l1 = g_pos_l1[tid];
        gi = g_pos_gi[tid];
        cf += g_pos_cf[tid];
        np = g_pos_cnt[tid];
    }

    __shared__ double sd[256];
    __shared__ int    sn[256];
    sd[tid] = l1; __syncthreads();
    for (int s = 128; s > 0; s >>= 1) { if (tid < s) sd[tid] += sd[tid + s]; __syncthreads(); }
    l1 = sd[0]; __syncthreads();
    sd[tid] = gi; __syncthreads();
    for (int s = 128; s > 0; s >>= 1) { if (tid < s) sd[tid] += sd[tid + s]; __syncthreads(); }
    gi = sd[0]; __syncthreads();
    sd[tid] = cf; __syncthreads();
    for (int s = 128; s > 0; s >>= 1) { if (tid < s) sd[tid] += sd[tid + s]; __syncthreads(); }
    cf = sd[0]; __syncthreads();
    sn[tid] = np; __syncthreads();
    for (int s = 128; s > 0; s >>= 1) { if (tid < s) sn[tid] += sn[tid + s]; __syncthreads(); }
    np = sn[0];

    if (tid == 0) {
        float denom = (float)(np > 1 ? np : 1);
        float fl1 = (float)l1 / denom;
        float fgi = (float)gi / denom;
        float fcf = (float)(cf / (double)TOT_);
        out[0] = fl1;
        out[1] = fgi;
        out[2] = fcf;
        out[3] = fl1 + 2.0f * fgi + fcf;
        out[4] = (float)np / (float)TOT_;
        g_done = 0;   // reset for next replay
    }
}

extern "C" void kernel_launch(void* const* d_in, const int* in_sizes, int n_in,
                              void* d_out, int out_size) {
    const float* pred = (const float*)d_in[0];   // [B,C,H,W,4]
    const float* conf = (const float*)d_in[1];   // [B,C,H,W]
    // d_in[2] = cam (unused by the loss)
    const float* gtb  = (const float*)d_in[3];   // [B,N,4]
    const int*   gtl  = (const int*)d_in[4];     // [B,N]
    float* out = (float*)d_out;

    fused_kernel<<<GRID_BLOCKS, 256>>>(pred, conf, gtb, gtl, out);
}